// round 2
// baseline (speedup 1.0000x reference)
#include <cuda_runtime.h>

// Problem constants (fixed shapes from setup_inputs)
#define BB 64
#define CC 3
#define HH 224
#define WW 224
#define CW (CC * WW)          // 672
#define NN 224                // Gram size
#define TAIL 45               // 224 - int(0.8*224) = 224 - 179
#define NSWEEP 12             // cap; early-exit usually triggers sooner

// Scratch (device globals: allocation-free per harness rules)
__device__ float g_A[BB * HH * CW];     // masked, scaled input  [b][h][cw]
__device__ float g_G[BB * NN * NN];     // Gram A A^T per image
__device__ float g_Ut[BB * TAIL * NN];  // tail eigenvectors, row t = u_t^T
__device__ int   g_cnt[BB];             // observed-entry counts

// ---------------------------------------------------------------------------
// K1: A = (2x-1)*mask in [B,H,CW] layout; per-image mask count via atomics.
// HH*CW = 150528 is a multiple of 256, so each block lies inside one image.
// ---------------------------------------------------------------------------
__global__ void build_kernel(const float* __restrict__ x,
                             const int* __restrict__ mask) {
    int idx = blockIdx.x * 256 + threadIdx.x;
    int b   = idx / (HH * CW);
    int rem = idx - b * (HH * CW);
    int h   = rem / CW;
    int cw  = rem - h * CW;
    int c   = cw / WW;
    int w   = cw - c * WW;

    int m = mask[idx];
    float xv = x[((b * CC + c) * HH + h) * WW + w];
    g_A[idx] = m ? (2.0f * xv - 1.0f) : 0.0f;

    // block-level reduce of mask bits -> one integer atomic (deterministic)
    int s = m;
    #pragma unroll
    for (int o = 16; o; o >>= 1) s += __shfl_xor_sync(0xffffffffu, s, o);
    __shared__ int ss[8];
    int warp = threadIdx.x >> 5, lane = threadIdx.x & 31;
    if (lane == 0) ss[warp] = s;
    __syncthreads();
    if (threadIdx.x == 0) {
        int t = 0;
        #pragma unroll
        for (int i = 0; i < 8; i++) t += ss[i];
        atomicAdd(&g_cnt[b], t);
    }
}

// ---------------------------------------------------------------------------
// K2: G = A A^T per image. grid (7,7,BB), block (16,16), 2x2 micro-tile.
// ---------------------------------------------------------------------------
__global__ void gram_kernel() {
    __shared__ float As[32][33];
    __shared__ float Bs[32][33];
    int b  = blockIdx.z;
    int i0 = blockIdx.y * 32, j0 = blockIdx.x * 32;
    const float* Ab = g_A + (size_t)b * HH * CW;
    int tx = threadIdx.x, ty = threadIdx.y;
    int t = ty * 16 + tx;

    float a00 = 0.f, a01 = 0.f, a10 = 0.f, a11 = 0.f;
    for (int k0 = 0; k0 < CW; k0 += 32) {
        #pragma unroll
        for (int q = 0; q < 4; q++) {
            int e = t + q * 256;
            int rr = e >> 5, kk = e & 31;
            As[rr][kk] = Ab[(i0 + rr) * CW + k0 + kk];
            Bs[rr][kk] = Ab[(j0 + rr) * CW + k0 + kk];
        }
        __syncthreads();
        #pragma unroll
        for (int kk = 0; kk < 32; kk++) {
            float x0 = As[2 * ty][kk], x1 = As[2 * ty + 1][kk];
            float y0 = Bs[2 * tx][kk], y1 = Bs[2 * tx + 1][kk];
            a00 += x0 * y0; a01 += x0 * y1;
            a10 += x1 * y0; a11 += x1 * y1;
        }
        __syncthreads();
    }
    float* Gb = g_G + (size_t)b * NN * NN;
    Gb[(i0 + 2 * ty    ) * NN + j0 + 2 * tx    ] = a00;
    Gb[(i0 + 2 * ty    ) * NN + j0 + 2 * tx + 1] = a01;
    Gb[(i0 + 2 * ty + 1) * NN + j0 + 2 * tx    ] = a10;
    Gb[(i0 + 2 * ty + 1) * NN + j0 + 2 * tx + 1] = a11;
}

// ---------------------------------------------------------------------------
// K3: one-sided (Hestenes) Jacobi on G (columns in shared, col-major).
// G = U L U^T (PSD): at convergence column c = lambda_c * u_c. One CTA per
// image, 1024 threads, one warp per rotation pair. Round-robin tournament
// pairing: round r pairs (223, r) and ((r+p) mod 223, (r-p) mod 223).
// Early exit when a full sweep performs zero rotations.
// ---------------------------------------------------------------------------
__global__ void __launch_bounds__(1024, 1) jacobi_kernel() {
    extern __shared__ float sm[];
    float* W   = sm;                    // NN*NN, column-major
    float* nrm = sm + NN * NN;          // NN squared norms (= lambda^2)
    int*   rnk = (int*)(nrm + NN);      // NN ranks
    __shared__ int rot_flag;

    int b = blockIdx.x;
    int tid = threadIdx.x, warp = tid >> 5, lane = tid & 31;
    const float* Gb = g_G + (size_t)b * NN * NN;

    for (int i = tid; i < NN * NN; i += 1024) W[i] = Gb[i];
    __syncthreads();

    for (int sw = 0; sw < NSWEEP; ++sw) {
        if (tid == 0) rot_flag = 0;
        __syncthreads();
        for (int r = 0; r < NN - 1; ++r) {
            #pragma unroll
            for (int q = 0; q < 4; ++q) {
                int p = warp + (q << 5);
                if (p < NN / 2) {
                    int i, j;
                    if (p == 0) { i = NN - 1; j = r; }
                    else {
                        i = r + p; if (i >= NN - 1) i -= (NN - 1);
                        j = r - p; if (j < 0)       j += (NN - 1);
                    }
                    float* ci = W + i * NN;
                    float* cj = W + j * NN;
                    float wi[7], wj[7];
                    float pp = 0.f, qi = 0.f, qj = 0.f;
                    #pragma unroll
                    for (int m = 0; m < 7; m++) {
                        int rr = lane + 32 * m;
                        float a = ci[rr], d = cj[rr];
                        wi[m] = a; wj[m] = d;
                        pp += a * d; qi += a * a; qj += d * d;
                    }
                    #pragma unroll
                    for (int o = 16; o; o >>= 1) {
                        pp += __shfl_xor_sync(0xffffffffu, pp, o);
                        qi += __shfl_xor_sync(0xffffffffu, qi, o);
                        qj += __shfl_xor_sync(0xffffffffu, qj, o);
                    }
                    if (pp * pp > 1e-14f * qi * qj) {
                        if (lane == 0) rot_flag = 1;
                        float tau = (qj - qi) / (2.0f * pp);
                        float tt = 1.0f / (fabsf(tau) + sqrtf(1.0f + tau * tau));
                        if (tau < 0.f) tt = -tt;
                        float c = rsqrtf(1.0f + tt * tt);
                        float s = c * tt;
                        #pragma unroll
                        for (int m = 0; m < 7; m++) {
                            int rr = lane + 32 * m;
                            ci[rr] = c * wi[m] - s * wj[m];
                            cj[rr] = s * wi[m] + c * wj[m];
                        }
                    }
                }
            }
            __syncthreads();
        }
        if (rot_flag == 0) break;   // converged: all pairs under threshold
        __syncthreads();
    }

    // column squared norms: one warp per 7 columns
    #pragma unroll
    for (int k = 0; k < 7; k++) {
        int col = warp + 32 * k;
        const float* cc = W + col * NN;
        float s = 0.f;
        #pragma unroll
        for (int m = 0; m < 7; m++) { float v = cc[lane + 32 * m]; s += v * v; }
        #pragma unroll
        for (int o = 16; o; o >>= 1) s += __shfl_xor_sync(0xffffffffu, s, o);
        if (lane == 0) nrm[col] = s;
    }
    __syncthreads();

    // rank of each column (0 = smallest norm), deterministic tie-break
    if (tid < NN) {
        float mine = nrm[tid];
        int rk = 0;
        for (int j = 0; j < NN; j++) {
            float o = nrm[j];
            rk += (o < mine) || (o == mine && j < tid);
        }
        rnk[tid] = rk;
    }
    __syncthreads();

    // write normalized tail-45 eigenvectors (rows of Ut^T), coalesced
    for (int t = 0; t < NN; t++) {
        int rk = rnk[t];
        if (rk < TAIL) {
            float inv = rsqrtf(nrm[t]);   // 1/lambda: normalizes lambda*u -> u
            for (int rr = tid; rr < NN; rr += 1024)
                g_Ut[((size_t)b * TAIL + rk) * NN + rr] = W[t * NN + rr] * inv;
        }
    }
}

// ---------------------------------------------------------------------------
// K4: R = A - Ut (Ut^T A); epilogue: /p_obs, clip, (r+1)/2, scatter to NCHW.
// One CTA per image, 672 threads (one per output column cw). T accumulated in
// 45 registers/thread. float4 SMEM loads keep it FMA-bound.
// ---------------------------------------------------------------------------
__global__ void __launch_bounds__(672, 1) recon_kernel(float* __restrict__ out) {
    __shared__ __align__(16) float sU[TAIL * NN];
    int b = blockIdx.x, tid = threadIdx.x;
    const float* Ub = g_Ut + (size_t)b * TAIL * NN;
    for (int i = tid; i < TAIL * NN; i += 672) sU[i] = Ub[i];
    __syncthreads();

    const float* Ab = g_A + (size_t)b * HH * CW;
    float inv_p = (float)(HH * CW) / (float)g_cnt[b];

    float acc[TAIL];
    #pragma unroll
    for (int t = 0; t < TAIL; t++) acc[t] = 0.f;

    // pass 1: T[t] = sum_h U[h][t] * A[h][cw]   (thread owns cw)
    for (int h = 0; h < HH; h += 4) {
        float a0 = Ab[(h + 0) * CW + tid];
        float a1 = Ab[(h + 1) * CW + tid];
        float a2 = Ab[(h + 2) * CW + tid];
        float a3 = Ab[(h + 3) * CW + tid];
        #pragma unroll
        for (int t = 0; t < TAIL; t++) {
            float4 u = *(const float4*)&sU[t * NN + h];
            acc[t] += u.x * a0 + u.y * a1 + u.z * a2 + u.w * a3;
        }
    }

    int c = tid / WW, w = tid - c * WW;
    float* ob = out + (((size_t)b * CC + c) * HH) * WW + w;

    // pass 2: R[h] = A[h] - sum_t U[h][t] * T[t]; fused epilogue + scatter
    for (int h = 0; h < HH; h += 4) {
        float a0 = Ab[(h + 0) * CW + tid];
        float a1 = Ab[(h + 1) * CW + tid];
        float a2 = Ab[(h + 2) * CW + tid];
        float a3 = Ab[(h + 3) * CW + tid];
        float s0 = 0.f, s1 = 0.f, s2 = 0.f, s3 = 0.f;
        #pragma unroll
        for (int t = 0; t < TAIL; t++) {
            float4 u = *(const float4*)&sU[t * NN + h];
            float tv = acc[t];
            s0 += u.x * tv; s1 += u.y * tv; s2 += u.z * tv; s3 += u.w * tv;
        }
        float r0 = (a0 - s0) * inv_p;
        float r1 = (a1 - s1) * inv_p;
        float r2 = (a2 - s2) * inv_p;
        float r3 = (a3 - s3) * inv_p;
        r0 = fminf(1.f, fmaxf(-1.f, r0));
        r1 = fminf(1.f, fmaxf(-1.f, r1));
        r2 = fminf(1.f, fmaxf(-1.f, r2));
        r3 = fminf(1.f, fmaxf(-1.f, r3));
        ob[(h + 0) * WW] = 0.5f * r0 + 0.5f;
        ob[(h + 1) * WW] = 0.5f * r1 + 0.5f;
        ob[(h + 2) * WW] = 0.5f * r2 + 0.5f;
        ob[(h + 3) * WW] = 0.5f * r3 + 0.5f;
    }
}

// ---------------------------------------------------------------------------
extern "C" void kernel_launch(void* const* d_in, const int* in_sizes, int n_in,
                              void* d_out, int out_size) {
    const float* x    = (const float*)d_in[0];
    const int*   mask = (const int*)d_in[1];
    float*       out  = (float*)d_out;

    const int JAC_SMEM = (NN * NN + NN) * (int)sizeof(float) + NN * (int)sizeof(int);

    void* cntp = nullptr;
    cudaGetSymbolAddress(&cntp, g_cnt);
    cudaMemsetAsync(cntp, 0, BB * sizeof(int));

    cudaFuncSetAttribute(jacobi_kernel,
                         cudaFuncAttributeMaxDynamicSharedMemorySize, JAC_SMEM);

    build_kernel<<<BB * HH * CW / 256, 256>>>(x, mask);
    gram_kernel<<<dim3(7, 7, BB), dim3(16, 16)>>>();
    jacobi_kernel<<<BB, 1024, JAC_SMEM>>>();
    recon_kernel<<<BB, 672>>>(out);
}

// round 3
// speedup vs baseline: 1.2951x; 1.2951x over previous
#include <cuda_runtime.h>

// Problem constants (fixed shapes from setup_inputs)
#define BB 64
#define CC 3
#define HH 224
#define WW 224
#define CW (CC * WW)          // 672
#define NN 224                // Gram size
#define TAIL 45               // 224 - int(0.8*224)
#define NSWEEP 9              // cap; early-exit usually sooner
#define THR 1e-12f            // relative skip threshold (cos^2)

// Scratch (device globals: allocation-free per harness rules)
__device__ float g_A[BB * HH * CW];     // masked, scaled input  [b][h][cw]
__device__ float g_G[BB * NN * NN];     // Gram A A^T per image
__device__ float g_Ut[BB * TAIL * NN];  // tail eigenvectors, row t = u_t^T
__device__ int   g_cnt[BB];             // observed-entry counts

// ---------------------------------------------------------------------------
// K1: A = (2x-1)*mask in [B,H,CW] layout; per-image mask count via atomics.
// ---------------------------------------------------------------------------
__global__ void build_kernel(const float* __restrict__ x,
                             const int* __restrict__ mask) {
    int idx = blockIdx.x * 256 + threadIdx.x;
    int b   = idx / (HH * CW);
    int rem = idx - b * (HH * CW);
    int h   = rem / CW;
    int cw  = rem - h * CW;
    int c   = cw / WW;
    int w   = cw - c * WW;

    int m = mask[idx];
    float xv = x[((b * CC + c) * HH + h) * WW + w];
    g_A[idx] = m ? (2.0f * xv - 1.0f) : 0.0f;

    int s = m;
    #pragma unroll
    for (int o = 16; o; o >>= 1) s += __shfl_xor_sync(0xffffffffu, s, o);
    __shared__ int ss[8];
    int warp = threadIdx.x >> 5, lane = threadIdx.x & 31;
    if (lane == 0) ss[warp] = s;
    __syncthreads();
    if (threadIdx.x == 0) {
        int t = 0;
        #pragma unroll
        for (int i = 0; i < 8; i++) t += ss[i];
        atomicAdd(&g_cnt[b], t);
    }
}

// ---------------------------------------------------------------------------
// K2: G = A A^T per image. grid (7,7,BB), block (16,16), 2x2 micro-tile.
// ---------------------------------------------------------------------------
__global__ void gram_kernel() {
    __shared__ float As[32][33];
    __shared__ float Bs[32][33];
    int b  = blockIdx.z;
    int i0 = blockIdx.y * 32, j0 = blockIdx.x * 32;
    const float* Ab = g_A + (size_t)b * HH * CW;
    int tx = threadIdx.x, ty = threadIdx.y;
    int t = ty * 16 + tx;

    float a00 = 0.f, a01 = 0.f, a10 = 0.f, a11 = 0.f;
    for (int k0 = 0; k0 < CW; k0 += 32) {
        #pragma unroll
        for (int q = 0; q < 4; q++) {
            int e = t + q * 256;
            int rr = e >> 5, kk = e & 31;
            As[rr][kk] = Ab[(i0 + rr) * CW + k0 + kk];
            Bs[rr][kk] = Ab[(j0 + rr) * CW + k0 + kk];
        }
        __syncthreads();
        #pragma unroll
        for (int kk = 0; kk < 32; kk++) {
            float x0 = As[2 * ty][kk], x1 = As[2 * ty + 1][kk];
            float y0 = Bs[2 * tx][kk], y1 = Bs[2 * tx + 1][kk];
            a00 += x0 * y0; a01 += x0 * y1;
            a10 += x1 * y0; a11 += x1 * y1;
        }
        __syncthreads();
    }
    float* Gb = g_G + (size_t)b * NN * NN;
    Gb[(i0 + 2 * ty    ) * NN + j0 + 2 * tx    ] = a00;
    Gb[(i0 + 2 * ty    ) * NN + j0 + 2 * tx + 1] = a01;
    Gb[(i0 + 2 * ty + 1) * NN + j0 + 2 * tx    ] = a10;
    Gb[(i0 + 2 * ty + 1) * NN + j0 + 2 * tx + 1] = a11;
}

// ---------------------------------------------------------------------------
// K3: one-sided (Hestenes) Jacobi on G with incrementally-maintained column
// norms. One CTA per image, 1024 threads; warps process pairs two-at-a-time
// (pairs within a round are disjoint). Tournament pairing:
// round r: pair0 = (223, r); pair p: ((r+p) mod 223, (r-p) mod 223).
// ---------------------------------------------------------------------------
__device__ __forceinline__ void pair_ij(int r, int p, int& i, int& j) {
    if (p == 0) { i = NN - 1; j = r; }
    else {
        i = r + p; if (i >= NN - 1) i -= (NN - 1);
        j = r - p; if (j < 0)       j += (NN - 1);
    }
}

__global__ void __launch_bounds__(1024, 1) jacobi_kernel() {
    extern __shared__ float sm[];
    float* W   = sm;                    // NN*NN, column-major
    float* nrm = sm + NN * NN;          // NN squared norms (maintained)
    int*   rnk = (int*)(nrm + NN);      // NN ranks
    __shared__ int rot_flag;

    int b = blockIdx.x;
    int tid = threadIdx.x, warp = tid >> 5, lane = tid & 31;
    const float* Gb = g_G + (size_t)b * NN * NN;

    for (int i = tid; i < NN * NN; i += 1024) W[i] = Gb[i];
    __syncthreads();

    // initial column squared norms
    #pragma unroll
    for (int k = 0; k < 7; k++) {
        int col = warp + 32 * k;
        const float* cc = W + col * NN;
        float s = 0.f;
        #pragma unroll
        for (int m = 0; m < 7; m++) { float v = cc[lane + 32 * m]; s += v * v; }
        #pragma unroll
        for (int o = 16; o; o >>= 1) s += __shfl_xor_sync(0xffffffffu, s, o);
        if (lane == 0) nrm[col] = s;
    }
    __syncthreads();

    for (int sw = 0; sw < NSWEEP; ++sw) {
        if (tid == 0) rot_flag = 0;
        __syncthreads();
        for (int r = 0; r < NN - 1; ++r) {
            // two interleaved waves of pairs: {warp, warp+32} then
            // {warp+64, warp+96(<112)}
            #pragma unroll
            for (int wave = 0; wave < 2; ++wave) {
                int pA = warp + (wave ? 64 : 0);
                int pB = pA + 32;
                bool vB = (pB < NN / 2);       // warp-uniform

                int iA, jA, iB = 0, jB = 0;
                pair_ij(r, pA, iA, jA);
                if (vB) pair_ij(r, pB, iB, jB);

                float* ciA = W + iA * NN;  float* cjA = W + jA * NN;
                float* ciB = W + iB * NN;  float* cjB = W + jB * NN;

                float wiA[7], wjA[7], wiB[7], wjB[7];
                float ppA = 0.f, ppB = 0.f;
                #pragma unroll
                for (int m = 0; m < 7; m++) {
                    int rr = lane + 32 * m;
                    float a = ciA[rr], d = cjA[rr];
                    wiA[m] = a; wjA[m] = d; ppA += a * d;
                }
                if (vB) {
                    #pragma unroll
                    for (int m = 0; m < 7; m++) {
                        int rr = lane + 32 * m;
                        float a = ciB[rr], d = cjB[rr];
                        wiB[m] = a; wjB[m] = d; ppB += a * d;
                    }
                }
                #pragma unroll
                for (int o = 16; o; o >>= 1) {
                    ppA += __shfl_xor_sync(0xffffffffu, ppA, o);
                    ppB += __shfl_xor_sync(0xffffffffu, ppB, o);
                }

                float qiA = nrm[iA], qjA = nrm[jA];
                if (ppA * ppA > THR * qiA * qjA) {
                    if (lane == 0) rot_flag = 1;
                    float tau = (qjA - qiA) / (2.0f * ppA);
                    float tt = 1.0f / (fabsf(tau) + sqrtf(1.0f + tau * tau));
                    if (tau < 0.f) tt = -tt;
                    float c = rsqrtf(1.0f + tt * tt);
                    float s = c * tt;
                    #pragma unroll
                    for (int m = 0; m < 7; m++) {
                        int rr = lane + 32 * m;
                        ciA[rr] = c * wiA[m] - s * wjA[m];
                        cjA[rr] = s * wiA[m] + c * wjA[m];
                    }
                    if (lane == 0) {
                        float c2 = c * c, s2 = s * s, cs2 = 2.f * c * s;
                        nrm[iA] = c2 * qiA - cs2 * ppA + s2 * qjA;
                        nrm[jA] = s2 * qiA + cs2 * ppA + c2 * qjA;
                    }
                }
                if (vB) {
                    float qiB = nrm[iB], qjB = nrm[jB];
                    if (ppB * ppB > THR * qiB * qjB) {
                        if (lane == 0) rot_flag = 1;
                        float tau = (qjB - qiB) / (2.0f * ppB);
                        float tt = 1.0f / (fabsf(tau) + sqrtf(1.0f + tau * tau));
                        if (tau < 0.f) tt = -tt;
                        float c = rsqrtf(1.0f + tt * tt);
                        float s = c * tt;
                        #pragma unroll
                        for (int m = 0; m < 7; m++) {
                            int rr = lane + 32 * m;
                            ciB[rr] = c * wiB[m] - s * wjB[m];
                            cjB[rr] = s * wiB[m] + c * wjB[m];
                        }
                        if (lane == 0) {
                            float c2 = c * c, s2 = s * s, cs2 = 2.f * c * s;
                            nrm[iB] = c2 * qiB - cs2 * ppB + s2 * qjB;
                            nrm[jB] = s2 * qiB + cs2 * ppB + c2 * qjB;
                        }
                    }
                }
            }
            __syncthreads();
        }
        if (rot_flag == 0) break;
        __syncthreads();
    }

    // rank of each column (0 = smallest norm), deterministic tie-break
    if (tid < NN) {
        float mine = nrm[tid];
        int rk = 0;
        for (int j = 0; j < NN; j++) {
            float o = nrm[j];
            rk += (o < mine) || (o == mine && j < tid);
        }
        rnk[tid] = rk;
    }
    __syncthreads();

    // write normalized tail-45 eigenvectors (rows of Ut^T), coalesced
    for (int t = 0; t < NN; t++) {
        int rk = rnk[t];
        if (rk < TAIL) {
            float inv = rsqrtf(nrm[t]);   // 1/lambda
            for (int rr = tid; rr < NN; rr += 1024)
                g_Ut[((size_t)b * TAIL + rk) * NN + rr] = W[t * NN + rr] * inv;
        }
    }
}

// ---------------------------------------------------------------------------
// K4: R = A - Ut (Ut^T A); epilogue: /p_obs, clip, (r+1)/2, scatter to NCHW.
// Two CTAs per image (336 columns each), T in 45 registers/thread.
// ---------------------------------------------------------------------------
__global__ void __launch_bounds__(336, 2) recon_kernel(float* __restrict__ out) {
    __shared__ __align__(16) float sU[TAIL * NN];
    int b = blockIdx.x >> 1, half = blockIdx.x & 1;
    int tid = threadIdx.x;
    int cw  = half * 336 + tid;
    const float* Ub = g_Ut + (size_t)b * TAIL * NN;
    for (int i = tid; i < TAIL * NN; i += 336) sU[i] = Ub[i];
    __syncthreads();

    const float* Ab = g_A + (size_t)b * HH * CW;
    float inv_p = (float)(HH * CW) / (float)g_cnt[b];

    float acc[TAIL];
    #pragma unroll
    for (int t = 0; t < TAIL; t++) acc[t] = 0.f;

    // pass 1: T[t] = sum_h U[h][t] * A[h][cw]
    for (int h = 0; h < HH; h += 4) {
        float a0 = Ab[(h + 0) * CW + cw];
        float a1 = Ab[(h + 1) * CW + cw];
        float a2 = Ab[(h + 2) * CW + cw];
        float a3 = Ab[(h + 3) * CW + cw];
        #pragma unroll
        for (int t = 0; t < TAIL; t++) {
            float4 u = *(const float4*)&sU[t * NN + h];
            acc[t] += u.x * a0 + u.y * a1 + u.z * a2 + u.w * a3;
        }
    }

    int c = cw / WW, w = cw - c * WW;
    float* ob = out + (((size_t)b * CC + c) * HH) * WW + w;

    // pass 2: R[h] = A[h] - sum_t U[h][t] * T[t]; fused epilogue + scatter
    for (int h = 0; h < HH; h += 4) {
        float a0 = Ab[(h + 0) * CW + cw];
        float a1 = Ab[(h + 1) * CW + cw];
        float a2 = Ab[(h + 2) * CW + cw];
        float a3 = Ab[(h + 3) * CW + cw];
        float s0 = 0.f, s1 = 0.f, s2 = 0.f, s3 = 0.f;
        #pragma unroll
        for (int t = 0; t < TAIL; t++) {
            float4 u = *(const float4*)&sU[t * NN + h];
            float tv = acc[t];
            s0 += u.x * tv; s1 += u.y * tv; s2 += u.z * tv; s3 += u.w * tv;
        }
        float r0 = (a0 - s0) * inv_p;
        float r1 = (a1 - s1) * inv_p;
        float r2 = (a2 - s2) * inv_p;
        float r3 = (a3 - s3) * inv_p;
        r0 = fminf(1.f, fmaxf(-1.f, r0));
        r1 = fminf(1.f, fmaxf(-1.f, r1));
        r2 = fminf(1.f, fmaxf(-1.f, r2));
        r3 = fminf(1.f, fmaxf(-1.f, r3));
        ob[(h + 0) * WW] = 0.5f * r0 + 0.5f;
        ob[(h + 1) * WW] = 0.5f * r1 + 0.5f;
        ob[(h + 2) * WW] = 0.5f * r2 + 0.5f;
        ob[(h + 3) * WW] = 0.5f * r3 + 0.5f;
    }
}

// ---------------------------------------------------------------------------
extern "C" void kernel_launch(void* const* d_in, const int* in_sizes, int n_in,
                              void* d_out, int out_size) {
    const float* x    = (const float*)d_in[0];
    const int*   mask = (const int*)d_in[1];
    float*       out  = (float*)d_out;

    const int JAC_SMEM = (NN * NN + NN) * (int)sizeof(float) + NN * (int)sizeof(int);

    void* cntp = nullptr;
    cudaGetSymbolAddress(&cntp, g_cnt);
    cudaMemsetAsync(cntp, 0, BB * sizeof(int));

    cudaFuncSetAttribute(jacobi_kernel,
                         cudaFuncAttributeMaxDynamicSharedMemorySize, JAC_SMEM);

    build_kernel<<<BB * HH * CW / 256, 256>>>(x, mask);
    gram_kernel<<<dim3(7, 7, BB), dim3(16, 16)>>>();
    jacobi_kernel<<<BB, 1024, JAC_SMEM>>>();
    recon_kernel<<<2 * BB, 336>>>(out);
}